// round 1
// baseline (speedup 1.0000x reference)
#include <cuda_runtime.h>
#include <cstdint>

#define LOG2E 1.4426950408889634f

typedef unsigned long long u64;

__device__ __forceinline__ u64 f2fma(u64 a, u64 b, u64 c) {
    u64 r; asm("fma.rn.f32x2 %0,%1,%2,%3;" : "=l"(r) : "l"(a), "l"(b), "l"(c)); return r;
}
__device__ __forceinline__ u64 f2add(u64 a, u64 b) {
    u64 r; asm("add.rn.f32x2 %0,%1,%2;" : "=l"(r) : "l"(a), "l"(b)); return r;
}
__device__ __forceinline__ u64 pk(float lo, float hi) {
    u64 r; asm("mov.b64 %0,{%1,%2};" : "=l"(r) : "f"(lo), "f"(hi)); return r;
}
__device__ __forceinline__ void up(u64 v, float& lo, float& hi) {
    asm("mov.b64 {%0,%1},%2;" : "=f"(lo), "=f"(hi) : "l"(v));
}
__device__ __forceinline__ float ex2f(float x) {
    float r; asm("ex2.approx.f32 %0,%1;" : "=f"(r) : "f"(x)); return r;
}

__global__ void zero_out_kernel(float* out) { *out = 0.0f; }

// B=8, N=4096, M=4096, D=3 hardcoded.
// Grid: 128 blocks = 8 batches x 16 n-chunks. Block: 256 threads, 1 n each.
__global__ void __launch_bounds__(256) fape_kernel(
    const float* __restrict__ Xp,   // (8,4096,3)
    const float* __restrict__ Xt,   // (8,4096,3)
    const float* __restrict__ Rp,   // (8,3,3)
    const float* __restrict__ tp,   // (8,3)
    const float* __restrict__ Rt,   // (8,3,3)
    const float* __restrict__ tt,   // (8,3)
    const float* __restrict__ temp, // (1,)
    float* __restrict__ out)
{
    extern __shared__ float4 sm4[];
    float4* A  = sm4;          // 1024 x {vx_e, vx_o, vy_e, vy_o}
    float4* Bv = sm4 + 1024;   // 1024 x {vz_e, vz_o, vw_e, vw_o}

    const int b     = blockIdx.x >> 4;
    const int chunk = blockIdx.x & 15;
    const int tid   = threadIdx.x;
    const int n     = chunk * 256 + tid;

    const float T = *temp;
    const float s = -LOG2E / T;   // logit scale in log2 domain (s < 0)

    // R_true / t_true (kept in registers; also used by rare fallback path)
    const float* R = Rt + b * 9;
    const float* tv = tt + b * 3;
    const float r00 = R[0], r01 = R[1], r02 = R[2];
    const float r10 = R[3], r11 = R[4], r12 = R[5];
    const float r20 = R[6], r21 = R[7], r22 = R[8];
    const float tx = tv[0], ty = tv[1], tz = tv[2];

    // per-n setup: xp = R_pred x + t_pred
    const float* Rq = Rp + b * 9;
    const float* tq = tp + b * 3;
    const float* xpn = Xp + (size_t)(b * 4096 + n) * 3;
    const float qx = xpn[0], qy = xpn[1], qz = xpn[2];
    const float px = Rq[0] * qx + Rq[1] * qy + Rq[2] * qz + tq[0];
    const float py = Rq[3] * qx + Rq[4] * qy + Rq[5] * qz + tq[1];
    const float pz = Rq[6] * qx + Rq[7] * qy + Rq[8] * qz + tq[2];
    const float scn = s * (px * px + py * py + pz * pz);

    const u64 Px = pk(px, px), Py = pk(py, py), Pz = pk(pz, pz);
    const u64 Sc = pk(scn, scn);
    u64 Se = pk(0.0f, 0.0f);   // sum of exp (even/odd m lanes)
    u64 St = pk(0.0f, 0.0f);   // sum of exp * d'
    float mx0 = -3.4e38f, mx1 = -3.4e38f;

    const float* xtb = Xt + (size_t)b * 4096 * 3;

    for (int half = 0; half < 2; half++) {
        __syncthreads();  // all readers done with previous half before overwrite
        const int mbase = half * 2048;
        // Fill smem: v = (s*-2*xt, s*|xt|^2), paired even/odd layout
        for (int mi = tid; mi < 2048; mi += 256) {
            const int m = mbase + mi;
            const float x = xtb[m * 3 + 0], y = xtb[m * 3 + 1], z = xtb[m * 3 + 2];
            const float ax = r00 * x + r01 * y + r02 * z + tx;
            const float ay = r10 * x + r11 * y + r12 * z + ty;
            const float az = r20 * x + r21 * y + r22 * z + tz;
            const float sq = ax * ax + ay * ay + az * az;
            const float s2 = s * -2.0f;
            const int j = mi >> 1, h = mi & 1;
            float* aj = (float*)(A + j);
            float* bj = (float*)(Bv + j);
            aj[h]     = s2 * ax;
            aj[2 + h] = s2 * ay;
            bj[h]     = s2 * az;
            bj[2 + h] = s * sq;
        }
        __syncthreads();

        #pragma unroll 4
        for (int j = 0; j < 1024; j++) {
            const float4 a = A[j];
            const float4 c = Bv[j];
            const u64 vx = pk(a.x, a.y);
            const u64 vy = pk(a.z, a.w);
            const u64 vz = pk(c.x, c.y);
            const u64 vw = pk(c.z, c.w);
            u64 d = f2add(Sc, vw);         // s*(|xp|^2 + |xt|^2)
            d = f2fma(Pz, vz, d);
            d = f2fma(Py, vy, d);
            d = f2fma(Px, vx, d);          // d' = s * dist^2  (<= ~0)
            float d0, d1; up(d, d0, d1);
            mx0 = fmaxf(mx0, d0);          // ALU pipe, for underflow fallback
            mx1 = fmaxf(mx1, d1);
            const float e0 = ex2f(d0);
            const float e1 = ex2f(d1);
            const u64 E = pk(e0, e1);
            Se = f2add(Se, E);
            St = f2fma(E, d, St);
        }
    }

    float se0, se1, st0, st1;
    up(Se, se0, se1); up(St, st0, st1);
    float sumE = se0 + se1;
    float sumT = st0 + st1;
    const float mm = fmaxf(mx0, mx1);
    float sh = 0.0f;

    if (!(sumE > 0.0f)) {
        // Rare: all exps underflowed (min dist^2 > ~8.7). Redo shifted by max logit.
        sh = mm;
        sumE = 0.0f; sumT = 0.0f;
        const float base = scn - mm;
        const float s2 = s * -2.0f;
        for (int m = 0; m < 4096; m++) {
            const float x = xtb[m * 3 + 0], y = xtb[m * 3 + 1], z = xtb[m * 3 + 2];
            const float ax = r00 * x + r01 * y + r02 * z + tx;
            const float ay = r10 * x + r11 * y + r12 * z + ty;
            const float az = r20 * x + r21 * y + r22 * z + tz;
            const float sq = ax * ax + ay * ay + az * az;
            const float t = base + s * sq + s2 * (px * ax + py * ay + pz * az);
            const float e = ex2f(t);
            sumE += e;
            sumT += e * t;
        }
    }

    // weighted_n = sum(e*d)/sum(e), with d = (t + sh)/s
    const float invs = 1.0f / s;
    const float weighted = invs * (sumT / sumE + sh);

    // block reduce + atomic accumulate of the global mean
    __shared__ float red[256];
    red[tid] = weighted;
    __syncthreads();
    #pragma unroll
    for (int off = 128; off > 0; off >>= 1) {
        if (tid < off) red[tid] += red[tid + off];
        __syncthreads();
    }
    if (tid == 0) atomicAdd(out, red[0] * (1.0f / (8.0f * 4096.0f)));
}

extern "C" void kernel_launch(void* const* d_in, const int* in_sizes, int n_in,
                              void* d_out, int out_size) {
    const float* Xp   = (const float*)d_in[0];
    const float* Xt   = (const float*)d_in[1];
    const float* Rp   = (const float*)d_in[2];
    const float* tp   = (const float*)d_in[3];
    const float* Rt   = (const float*)d_in[4];
    const float* tt   = (const float*)d_in[5];
    const float* temp = (const float*)d_in[6];
    float* out = (float*)d_out;

    zero_out_kernel<<<1, 1>>>(out);
    const size_t smem = 2048 * sizeof(float4);  // 32 KB: two 16KB paired arrays
    fape_kernel<<<128, 256, smem>>>(Xp, Xt, Rp, tp, Rt, tt, temp, out);
}